// round 14
// baseline (speedup 1.0000x reference)
#include <cuda_runtime.h>
#include <math.h>

#define NN   400
#define FF   240
#define CC   32
#define LL   1440
#define JB_T 13     // ceil(400/32) j-tiles
#define IB_T 25     // 400/16 i-tiles
#define TI   16     // i rows per pair-kernel block

// ---------------- scratch (device globals; no allocation) ----------------
__device__ float g_e1[NN * NN];
__device__ float g_aggIpart[JB_T * NN * CC];
__device__ float g_aggJpart[IB_T * NN * CC];
__device__ float g_x1[NN * FF];
__device__ float g_x2[NN * FF];

// ---------------- fused pair kernel ----------------
// grid (JB_T, IB_T), block 256. lane -> j column, warp -> i rows (w, w+8).
// Computes Pi (16 i-rows) and Pj (32 j-rows) in-block from x and sw,
// time-sharing one smem arena between the x staging buffer and the
// per-warp transpose scratch (disjoint lifetimes, sync-separated).
__global__ __launch_bounds__(256)
void pair_kernel(const float* __restrict__ a, const float* __restrict__ e,
                 const float* __restrict__ x,
                 const float* __restrict__ sw, const float* __restrict__ sb,
                 const float* __restrict__ aiw, const float* __restrict__ aib,
                 const float* __restrict__ ajw, const float* __restrict__ ajb,
                 const float* __restrict__ ew,  const float* __restrict__ eb,
                 float* __restrict__ eout, int write_eout,
                 float* __restrict__ aggIpart, float* __restrict__ aggJpart) {
    int jb = blockIdx.x, ib = blockIdx.y;
    int t = threadIdx.x;
    int w = t >> 5, lane = t & 31;
    int j = jb * 32 + lane;
    bool jok = (j < NN);

    // arena: phase A/B -> x rows (max 32*240*4 = 30720 B); main loop -> sT (8*32*33*4 = 33792 B)
    __shared__ __align__(16) char arena[8 * 32 * 33 * 4];
    __shared__ float  sPi[TI][CC];
    __shared__ float  sPjS[32][33];
    __shared__ float4 sPack[CC];        // {sw480, sw481, aiw, ajw}
    __shared__ float  sew_[CC];
    __shared__ float  sET[TI * 33];     // e^T tile: sET[ii*33 + jl] = e[j, i]

    float* xb = reinterpret_cast<float*>(arena);

    if (t < CC) {
        sPack[t] = make_float4(sw[480 * CC + t], sw[481 * CC + t], aiw[t], ajw[t]);
        sew_[t] = ew[t];
    }
    // load + transpose the e[j, i] tile (32 j rows x 16 i cols)
    for (int idx = t; idx < 32 * TI; idx += 256) {
        int jl = idx >> 4, il = idx & 15;
        int jg = jb * 32 + jl;
        sET[il * 33 + jl] = (jg < NN) ? e[jg * NN + ib * TI + il] : 0.f;
    }
    // A1: stage the 32 j-rows of x (zero-fill OOB to avoid 0*NaN later)
    for (int idx = t; idx < 32 * FF; idx += 256) {
        int r = idx / FF, k = idx - r * FF;
        int g = jb * 32 + r;
        xb[idx] = (g < NN) ? x[g * FF + k] : 0.f;
    }
    __syncthreads();

    // B1: Pj = x_j @ sw[240:480]; warp w -> j-local rows 4w..4w+3, lane -> channel
    {
        const float* wb = sw + 240 * CC + lane;
        float acc[4] = {0.f, 0.f, 0.f, 0.f};
        int r0 = w * 4;
#pragma unroll 2
        for (int k = 0; k < FF; k += 4) {
            float w0 = wb[k * CC], w1 = wb[(k + 1) * CC];
            float w2 = wb[(k + 2) * CC], w3 = wb[(k + 3) * CC];
#pragma unroll
            for (int q = 0; q < 4; q++) {
                float4 xv = *reinterpret_cast<const float4*>(xb + (r0 + q) * FF + k);
                acc[q] = fmaf(xv.x, w0, fmaf(xv.y, w1, fmaf(xv.z, w2, fmaf(xv.w, w3, acc[q]))));
            }
        }
#pragma unroll
        for (int q = 0; q < 4; q++) sPjS[r0 + q][lane] = acc[q];
    }
    __syncthreads();

    // A2: stage the 16 i-rows of x (always in-bounds: ib*16+15 <= 399)
    for (int idx = t; idx < TI * FF; idx += 256) {
        int r = idx / FF, k = idx - r * FF;
        xb[idx] = x[(ib * TI + r) * FF + k];
    }
    __syncthreads();

    // B2: Pi = x_i @ sw[0:240] + sb; warp w -> i-local rows 2w, 2w+1
    {
        const float* wb = sw + lane;
        float acc0 = 0.f, acc1 = 0.f;
        int r0 = w * 2;
#pragma unroll 2
        for (int k = 0; k < FF; k += 4) {
            float w0 = wb[k * CC], w1 = wb[(k + 1) * CC];
            float w2 = wb[(k + 2) * CC], w3 = wb[(k + 3) * CC];
            float4 xv0 = *reinterpret_cast<const float4*>(xb + r0 * FF + k);
            float4 xv1 = *reinterpret_cast<const float4*>(xb + (r0 + 1) * FF + k);
            acc0 = fmaf(xv0.x, w0, fmaf(xv0.y, w1, fmaf(xv0.z, w2, fmaf(xv0.w, w3, acc0))));
            acc1 = fmaf(xv1.x, w0, fmaf(xv1.y, w1, fmaf(xv1.z, w2, fmaf(xv1.w, w3, acc1))));
        }
        float bias = sb[lane];
        sPi[r0][lane]     = acc0 + bias;
        sPi[r0 + 1][lane] = acc1 + bias;
    }
    __syncthreads();   // xb dead; arena becomes sT from here

    float pj[CC];
#pragma unroll
    for (int c = 0; c < CC; c++) pj[c] = sPjS[lane][c];   // conflict-free (stride 33)

    float aggj[CC];
#pragma unroll
    for (int c = 0; c < CC; c++) aggj[c] = 0.f;
    float aibv = aib[0], ajbv = ajb[0], ebv = eb[0];

    float* sTbase = reinterpret_cast<float*>(arena);
    float* myT = sTbase + w * (32 * 33);
    for (int ii = w; ii < TI; ii += 8) {
        int i = ib * TI + ii;
        float aij = jok ? a[i * NN + j] : 0.f;
        float eij = jok ? e[i * NN + j] : 0.f;
        float eji = sET[ii * 33 + lane];
        float d1 = aibv, d2 = ajbv, d3 = ebv;
        float s[CC];
#pragma unroll
        for (int c = 0; c < CC; c++) {
            float4 wp = sPack[c];
            float lin = sPi[ii][c] + pj[c] + eij * wp.x + eji * wp.y;
            float sc = fmaxf(lin, 0.f) * aij;
            s[c] = sc;
            d1 = fmaf(sc, wp.z, d1);
            d2 = fmaf(sc, wp.w, d2);
            d3 = fmaf(sc, sew_[c], d3);
        }
        float atti = 1.f / (1.f + __expf(-d1));
        float attj = 1.f / (1.f + __expf(-d2));
        if (write_eout && jok) eout[i * NN + j] = d3;
#pragma unroll
        for (int c = 0; c < CC; c++) {
            aggj[c] = fmaf(attj, s[c], aggj[c]);
            myT[lane * 33 + c] = atti * s[c];
        }
        __syncwarp();
        float acc = 0.f;
#pragma unroll
        for (int r = 0; r < 32; r++) acc += myT[r * 33 + lane];
        aggIpart[(jb * NN + i) * CC + lane] = acc;
        __syncwarp();
    }

    // cross-warp agg_j reduce
    __syncthreads();
#pragma unroll
    for (int c = 0; c < CC; c++) myT[lane * 33 + c] = aggj[c];
    __syncthreads();
    for (int idx = t; idx < 32 * CC; idx += 256) {
        int jl = idx >> 5, c = idx & 31;
        float v = 0.f;
#pragma unroll
        for (int ww = 0; ww < 8; ww++) v += sTbase[ww * (32 * 33) + jl * 33 + c];
        int jg = jb * 32 + jl;
        if (jg < NN) aggJpart[(ib * NN + jg) * CC + c] = v;
    }
}

// ---------------- node model (fused partial-reduce): xout = [x, aggI, aggJ] @ nw + nb
// grid 100 (4 rows/block), block 240 (one f each), 4 accumulators/thread
#define NIT 4
__global__ __launch_bounds__(240)
void node_kernel(const float* __restrict__ x,
                 const float* __restrict__ nw, const float* __restrict__ nb,
                 const float* __restrict__ aggIpart, const float* __restrict__ aggJpart,
                 float* __restrict__ xout) {
    int b = blockIdx.x, t = threadIdx.x;
    int i0 = b * NIT;
    __shared__ float row[NIT][304];
    // phase 0: reduce partial slabs into the concat columns
    for (int idx = t; idx < NIT * CC; idx += 240) {
        int il = idx >> 5, c = idx & 31;
        int i = i0 + il;
        float ai = 0.f;
#pragma unroll
        for (int p = 0; p < JB_T; p++) ai += aggIpart[(p * NN + i) * CC + c];
        row[il][240 + c] = ai;
        float aj = 0.f;
#pragma unroll
        for (int p = 0; p < IB_T; p++) aj += aggJpart[(p * NN + i) * CC + c];
        row[il][272 + c] = aj;
    }
    for (int idx = t; idx < NIT * FF; idx += 240) {
        int il = idx / FF, k = idx % FF;
        row[il][k] = x[(i0 + il) * FF + k];
    }
    __syncthreads();
    int f = t;
    float acc[NIT];
    float bias = nb[f];
#pragma unroll
    for (int r = 0; r < NIT; r++) acc[r] = bias;
#pragma unroll 4
    for (int k = 0; k < 304; k += 4) {
        float w0 = nw[k * FF + f], w1 = nw[(k + 1) * FF + f];
        float w2 = nw[(k + 2) * FF + f], w3 = nw[(k + 3) * FF + f];
#pragma unroll
        for (int r = 0; r < NIT; r++) {
            float4 xv = *reinterpret_cast<const float4*>(&row[r][k]);
            acc[r] = fmaf(xv.x, w0, fmaf(xv.y, w1, fmaf(xv.z, w2, fmaf(xv.w, w3, acc[r]))));
        }
    }
#pragma unroll
    for (int r = 0; r < NIT; r++) xout[(i0 + r) * FF + f] = acc[r];
}

// ---------------- dense head: out = x2 @ dw + db ----------------
// grid (50, 3): 8 rows x 480 cols per block, block 480, 8 accumulators/thread
#define DIT 8
__global__ __launch_bounds__(480)
void dense_kernel(const float* __restrict__ x,
                  const float* __restrict__ dw, const float* __restrict__ db,
                  float* __restrict__ out) {
    int b = blockIdx.x, t = threadIdx.x;
    int i0 = b * DIT;
    int l = blockIdx.y * 480 + t;
    __shared__ float row[DIT][FF];
    for (int idx = t; idx < DIT * FF; idx += 480) {
        int il = idx / FF, k = idx % FF;
        row[il][k] = x[(i0 + il) * FF + k];
    }
    __syncthreads();
    float acc[DIT];
    float bias = db[l];
#pragma unroll
    for (int r = 0; r < DIT; r++) acc[r] = bias;
#pragma unroll 4
    for (int k = 0; k < FF; k += 4) {
        float w0 = dw[k * LL + l], w1 = dw[(k + 1) * LL + l];
        float w2 = dw[(k + 2) * LL + l], w3 = dw[(k + 3) * LL + l];
#pragma unroll
        for (int r = 0; r < DIT; r++) {
            float4 xv = *reinterpret_cast<const float4*>(&row[r][k]);
            acc[r] = fmaf(xv.x, w0, fmaf(xv.y, w1, fmaf(xv.z, w2, fmaf(xv.w, w3, acc[r]))));
        }
    }
#pragma unroll
    for (int r = 0; r < DIT; r++) out[(i0 + r) * LL + l] = acc[r];
}

// ---------------- launch ----------------
extern "C" void kernel_launch(void* const* d_in, const int* in_sizes, int n_in,
                              void* d_out, int out_size) {
    const float* x  = (const float*)d_in[0];
    const float* a  = (const float*)d_in[1];
    const float* e  = (const float*)d_in[2];
    const float* c1_sw  = (const float*)d_in[3];
    const float* c1_sb  = (const float*)d_in[4];
    const float* c1_aiw = (const float*)d_in[5];
    const float* c1_aib = (const float*)d_in[6];
    const float* c1_ajw = (const float*)d_in[7];
    const float* c1_ajb = (const float*)d_in[8];
    const float* c1_nw  = (const float*)d_in[9];
    const float* c1_nb  = (const float*)d_in[10];
    const float* c1_ew  = (const float*)d_in[11];
    const float* c1_eb  = (const float*)d_in[12];
    const float* c2_sw  = (const float*)d_in[13];
    const float* c2_sb  = (const float*)d_in[14];
    const float* c2_aiw = (const float*)d_in[15];
    const float* c2_aib = (const float*)d_in[16];
    const float* c2_ajw = (const float*)d_in[17];
    const float* c2_ajb = (const float*)d_in[18];
    const float* c2_nw  = (const float*)d_in[19];
    const float* c2_nb  = (const float*)d_in[20];
    const float* c2_ew  = (const float*)d_in[21];
    const float* c2_eb  = (const float*)d_in[22];
    const float* dw     = (const float*)d_in[23];
    const float* db     = (const float*)d_in[24];
    float* out = (float*)d_out;

    float *pE1, *pAIp, *pAJp, *pX1, *pX2;
    cudaGetSymbolAddress((void**)&pE1,  g_e1);
    cudaGetSymbolAddress((void**)&pAIp, g_aggIpart);
    cudaGetSymbolAddress((void**)&pAJp, g_aggJpart);
    cudaGetSymbolAddress((void**)&pX1,  g_x1);
    cudaGetSymbolAddress((void**)&pX2,  g_x2);

    dim3 pgrid(JB_T, IB_T);

    // ---- layer 1 ----
    pair_kernel<<<pgrid, 256>>>(a, e, x, c1_sw, c1_sb,
                                c1_aiw, c1_aib, c1_ajw, c1_ajb, c1_ew, c1_eb,
                                pE1, 1, pAIp, pAJp);
    node_kernel<<<100, 240>>>(x, c1_nw, c1_nb, pAIp, pAJp, pX1);

    // ---- layer 2 (e_out unused downstream -> skipped) ----
    pair_kernel<<<pgrid, 256>>>(a, pE1, pX1, c2_sw, c2_sb,
                                c2_aiw, c2_aib, c2_ajw, c2_ajb, c2_ew, c2_eb,
                                nullptr, 0, pAIp, pAJp);
    node_kernel<<<100, 240>>>(pX1, c2_nw, c2_nb, pAIp, pAJp, pX2);

    // ---- dense head ----
    dim3 dgrid(50, 3);
    dense_kernel<<<dgrid, 480>>>(pX2, dw, db, out);
}

// round 15
// speedup vs baseline: 1.0858x; 1.0858x over previous
#include <cuda_runtime.h>
#include <math.h>

#define NN   400
#define FF   240
#define CC   32
#define LL   1440
#define JB_T 13     // ceil(400/32) j-tiles
#define IB_T 25     // 400/16 i-tiles
#define TI   16     // i rows per pair-kernel block

// ---------------- scratch (device globals; no allocation) ----------------
__device__ float g_e1[NN * NN];
__device__ float g_aggIpart[JB_T * NN * CC];
__device__ float g_aggJpart[IB_T * NN * CC];
__device__ float g_x1[NN * FF];
__device__ float g_x2[NN * FF];

// ---------------- fused pair kernel ----------------
// grid (JB_T, IB_T), block 256. lane -> j column, warp -> i rows (w, w+8).
// Computes Pi (16 i-rows) and Pj (32 j-rows) in-block from x and sw,
// time-sharing one smem arena between the x staging buffer and the
// per-warp transpose scratch (disjoint lifetimes, sync-separated).
__global__ __launch_bounds__(256)
void pair_kernel(const float* __restrict__ a, const float* __restrict__ e,
                 const float* __restrict__ x,
                 const float* __restrict__ sw, const float* __restrict__ sb,
                 const float* __restrict__ aiw, const float* __restrict__ aib,
                 const float* __restrict__ ajw, const float* __restrict__ ajb,
                 const float* __restrict__ ew,  const float* __restrict__ eb,
                 float* __restrict__ eout, int write_eout,
                 float* __restrict__ aggIpart, float* __restrict__ aggJpart) {
    int jb = blockIdx.x, ib = blockIdx.y;
    int t = threadIdx.x;
    int w = t >> 5, lane = t & 31;
    int j = jb * 32 + lane;
    bool jok = (j < NN);

    // arena: phase A/B -> x rows (max 32*240*4 = 30720 B); main loop -> sT (8*32*33*4 = 33792 B)
    __shared__ __align__(16) char arena[8 * 32 * 33 * 4];
    __shared__ float  sPi[TI][CC];
    __shared__ float  sPjS[32][33];
    __shared__ float4 sPack[CC];        // {sw480, sw481, aiw, ajw}
    __shared__ float  sew_[CC];
    __shared__ float  sET[TI * 33];     // e^T tile: sET[ii*33 + jl] = e[j, i]

    float* xb = reinterpret_cast<float*>(arena);

    if (t < CC) {
        sPack[t] = make_float4(sw[480 * CC + t], sw[481 * CC + t], aiw[t], ajw[t]);
        sew_[t] = ew[t];
    }
    // load + transpose the e[j, i] tile (32 j rows x 16 i cols)
    for (int idx = t; idx < 32 * TI; idx += 256) {
        int jl = idx >> 4, il = idx & 15;
        int jg = jb * 32 + jl;
        sET[il * 33 + jl] = (jg < NN) ? e[jg * NN + ib * TI + il] : 0.f;
    }
    // A1: stage the 32 j-rows of x (zero-fill OOB to avoid 0*NaN later)
    for (int idx = t; idx < 32 * FF; idx += 256) {
        int r = idx / FF, k = idx - r * FF;
        int g = jb * 32 + r;
        xb[idx] = (g < NN) ? x[g * FF + k] : 0.f;
    }
    __syncthreads();

    // B1: Pj = x_j @ sw[240:480]; warp w -> j-local rows 4w..4w+3, lane -> channel
    {
        const float* wb = sw + 240 * CC + lane;
        float acc[4] = {0.f, 0.f, 0.f, 0.f};
        int r0 = w * 4;
#pragma unroll 2
        for (int k = 0; k < FF; k += 4) {
            float w0 = wb[k * CC], w1 = wb[(k + 1) * CC];
            float w2 = wb[(k + 2) * CC], w3 = wb[(k + 3) * CC];
#pragma unroll
            for (int q = 0; q < 4; q++) {
                float4 xv = *reinterpret_cast<const float4*>(xb + (r0 + q) * FF + k);
                acc[q] = fmaf(xv.x, w0, fmaf(xv.y, w1, fmaf(xv.z, w2, fmaf(xv.w, w3, acc[q]))));
            }
        }
#pragma unroll
        for (int q = 0; q < 4; q++) sPjS[r0 + q][lane] = acc[q];
    }
    __syncthreads();

    // A2: stage the 16 i-rows of x (always in-bounds: ib*16+15 <= 399)
    for (int idx = t; idx < TI * FF; idx += 256) {
        int r = idx / FF, k = idx - r * FF;
        xb[idx] = x[(ib * TI + r) * FF + k];
    }
    __syncthreads();

    // B2: Pi = x_i @ sw[0:240] + sb; warp w -> i-local rows 2w, 2w+1
    {
        const float* wb = sw + lane;
        float acc0 = 0.f, acc1 = 0.f;
        int r0 = w * 2;
#pragma unroll 2
        for (int k = 0; k < FF; k += 4) {
            float w0 = wb[k * CC], w1 = wb[(k + 1) * CC];
            float w2 = wb[(k + 2) * CC], w3 = wb[(k + 3) * CC];
            float4 xv0 = *reinterpret_cast<const float4*>(xb + r0 * FF + k);
            float4 xv1 = *reinterpret_cast<const float4*>(xb + (r0 + 1) * FF + k);
            acc0 = fmaf(xv0.x, w0, fmaf(xv0.y, w1, fmaf(xv0.z, w2, fmaf(xv0.w, w3, acc0))));
            acc1 = fmaf(xv1.x, w0, fmaf(xv1.y, w1, fmaf(xv1.z, w2, fmaf(xv1.w, w3, acc1))));
        }
        float bias = sb[lane];
        sPi[r0][lane]     = acc0 + bias;
        sPi[r0 + 1][lane] = acc1 + bias;
    }
    __syncthreads();   // xb dead; arena becomes sT from here

    float pj[CC];
#pragma unroll
    for (int c = 0; c < CC; c++) pj[c] = sPjS[lane][c];   // conflict-free (stride 33)

    float aggj[CC];
#pragma unroll
    for (int c = 0; c < CC; c++) aggj[c] = 0.f;
    float aibv = aib[0], ajbv = ajb[0], ebv = eb[0];

    float* sTbase = reinterpret_cast<float*>(arena);
    float* myT = sTbase + w * (32 * 33);
    for (int ii = w; ii < TI; ii += 8) {
        int i = ib * TI + ii;
        float aij = jok ? a[i * NN + j] : 0.f;
        float eij = jok ? e[i * NN + j] : 0.f;
        float eji = sET[ii * 33 + lane];
        float d1 = aibv, d2 = ajbv, d3 = ebv;
        float s[CC];
#pragma unroll
        for (int c = 0; c < CC; c++) {
            float4 wp = sPack[c];
            float lin = sPi[ii][c] + pj[c] + eij * wp.x + eji * wp.y;
            float sc = fmaxf(lin, 0.f) * aij;
            s[c] = sc;
            d1 = fmaf(sc, wp.z, d1);
            d2 = fmaf(sc, wp.w, d2);
            d3 = fmaf(sc, sew_[c], d3);
        }
        float atti = 1.f / (1.f + __expf(-d1));
        float attj = 1.f / (1.f + __expf(-d2));
        if (write_eout && jok) eout[i * NN + j] = d3;
#pragma unroll
        for (int c = 0; c < CC; c++) {
            aggj[c] = fmaf(attj, s[c], aggj[c]);
            myT[lane * 33 + c] = atti * s[c];
        }
        __syncwarp();
        float acc = 0.f;
#pragma unroll
        for (int r = 0; r < 32; r++) acc += myT[r * 33 + lane];
        aggIpart[(jb * NN + i) * CC + lane] = acc;
        __syncwarp();
    }

    // cross-warp agg_j reduce
    __syncthreads();
#pragma unroll
    for (int c = 0; c < CC; c++) myT[lane * 33 + c] = aggj[c];
    __syncthreads();
    for (int idx = t; idx < 32 * CC; idx += 256) {
        int jl = idx >> 5, c = idx & 31;
        float v = 0.f;
#pragma unroll
        for (int ww = 0; ww < 8; ww++) v += sTbase[ww * (32 * 33) + jl * 33 + c];
        int jg = jb * 32 + jl;
        if (jg < NN) aggJpart[(ib * NN + jg) * CC + c] = v;
    }
}

// ---------------- node model (fused partial-reduce + 2-way k-split) ----------------
// xout = [x, aggI, aggJ] @ nw + nb
// grid 200 (2 rows/block), block 480 = 240 f-columns x 2 k-halves (152 k each).
#define NROWS 2
__global__ __launch_bounds__(480)
void node_kernel(const float* __restrict__ x,
                 const float* __restrict__ nw, const float* __restrict__ nb,
                 const float* __restrict__ aggIpart, const float* __restrict__ aggJpart,
                 float* __restrict__ xout) {
    int b = blockIdx.x, t = threadIdx.x;
    int i0 = b * NROWS;
    __shared__ float row[NROWS][304];
    __shared__ float sred[2][NROWS][240];
    // phase 0: reduce partial slabs into the concat columns (fixed order, deterministic)
    for (int idx = t; idx < NROWS * CC; idx += 480) {
        int il = idx >> 5, c = idx & 31;
        int i = i0 + il;
        float ai = 0.f;
#pragma unroll
        for (int p = 0; p < JB_T; p++) ai += aggIpart[(p * NN + i) * CC + c];
        row[il][240 + c] = ai;
        float aj = 0.f;
#pragma unroll
        for (int p = 0; p < IB_T; p++) aj += aggJpart[(p * NN + i) * CC + c];
        row[il][272 + c] = aj;
    }
    for (int idx = t; idx < NROWS * FF; idx += 480) {
        int il = idx / FF, k = idx - il * FF;
        row[il][k] = x[(i0 + il) * FF + k];
    }
    __syncthreads();
    int f = t % 240, kh = t / 240;      // kh in {0,1}; k-range [kh*152, kh*152+152)
    float acc0 = 0.f, acc1 = 0.f;
    int kbase = kh * 152;               // 152*4 B = 608 B, 16B-aligned for float4
#pragma unroll 4
    for (int kk = 0; kk < 152; kk += 4) {
        int k = kbase + kk;
        float w0 = nw[k * FF + f], w1 = nw[(k + 1) * FF + f];
        float w2 = nw[(k + 2) * FF + f], w3 = nw[(k + 3) * FF + f];
        float4 xv0 = *reinterpret_cast<const float4*>(&row[0][k]);
        float4 xv1 = *reinterpret_cast<const float4*>(&row[1][k]);
        acc0 = fmaf(xv0.x, w0, fmaf(xv0.y, w1, fmaf(xv0.z, w2, fmaf(xv0.w, w3, acc0))));
        acc1 = fmaf(xv1.x, w0, fmaf(xv1.y, w1, fmaf(xv1.z, w2, fmaf(xv1.w, w3, acc1))));
    }
    sred[kh][0][f] = acc0;
    sred[kh][1][f] = acc1;
    __syncthreads();
    // combine k-halves + bias; 480 threads cover 2 rows x 240 cols exactly
    {
        int r = t / 240, ff = t - r * 240;
        xout[(i0 + r) * FF + ff] = nb[ff] + sred[0][r][ff] + sred[1][r][ff];
    }
}

// ---------------- dense head: out = x2 @ dw + db ----------------
// grid (50, 3): 8 rows x 480 cols per block, block 480, 8 accumulators/thread
#define DIT 8
__global__ __launch_bounds__(480)
void dense_kernel(const float* __restrict__ x,
                  const float* __restrict__ dw, const float* __restrict__ db,
                  float* __restrict__ out) {
    int b = blockIdx.x, t = threadIdx.x;
    int i0 = b * DIT;
    int l = blockIdx.y * 480 + t;
    __shared__ float row[DIT][FF];
    for (int idx = t; idx < DIT * FF; idx += 480) {
        int il = idx / FF, k = idx % FF;
        row[il][k] = x[(i0 + il) * FF + k];
    }
    __syncthreads();
    float acc[DIT];
    float bias = db[l];
#pragma unroll
    for (int r = 0; r < DIT; r++) acc[r] = bias;
#pragma unroll 4
    for (int k = 0; k < FF; k += 4) {
        float w0 = dw[k * LL + l], w1 = dw[(k + 1) * LL + l];
        float w2 = dw[(k + 2) * LL + l], w3 = dw[(k + 3) * LL + l];
#pragma unroll
        for (int r = 0; r < DIT; r++) {
            float4 xv = *reinterpret_cast<const float4*>(&row[r][k]);
            acc[r] = fmaf(xv.x, w0, fmaf(xv.y, w1, fmaf(xv.z, w2, fmaf(xv.w, w3, acc[r]))));
        }
    }
#pragma unroll
    for (int r = 0; r < DIT; r++) out[(i0 + r) * LL + l] = acc[r];
}

// ---------------- launch ----------------
extern "C" void kernel_launch(void* const* d_in, const int* in_sizes, int n_in,
                              void* d_out, int out_size) {
    const float* x  = (const float*)d_in[0];
    const float* a  = (const float*)d_in[1];
    const float* e  = (const float*)d_in[2];
    const float* c1_sw  = (const float*)d_in[3];
    const float* c1_sb  = (const float*)d_in[4];
    const float* c1_aiw = (const float*)d_in[5];
    const float* c1_aib = (const float*)d_in[6];
    const float* c1_ajw = (const float*)d_in[7];
    const float* c1_ajb = (const float*)d_in[8];
    const float* c1_nw  = (const float*)d_in[9];
    const float* c1_nb  = (const float*)d_in[10];
    const float* c1_ew  = (const float*)d_in[11];
    const float* c1_eb  = (const float*)d_in[12];
    const float* c2_sw  = (const float*)d_in[13];
    const float* c2_sb  = (const float*)d_in[14];
    const float* c2_aiw = (const float*)d_in[15];
    const float* c2_aib = (const float*)d_in[16];
    const float* c2_ajw = (const float*)d_in[17];
    const float* c2_ajb = (const float*)d_in[18];
    const float* c2_nw  = (const float*)d_in[19];
    const float* c2_nb  = (const float*)d_in[20];
    const float* c2_ew  = (const float*)d_in[21];
    const float* c2_eb  = (const float*)d_in[22];
    const float* dw     = (const float*)d_in[23];
    const float* db     = (const float*)d_in[24];
    float* out = (float*)d_out;

    float *pE1, *pAIp, *pAJp, *pX1, *pX2;
    cudaGetSymbolAddress((void**)&pE1,  g_e1);
    cudaGetSymbolAddress((void**)&pAIp, g_aggIpart);
    cudaGetSymbolAddress((void**)&pAJp, g_aggJpart);
    cudaGetSymbolAddress((void**)&pX1,  g_x1);
    cudaGetSymbolAddress((void**)&pX2,  g_x2);

    dim3 pgrid(JB_T, IB_T);

    // ---- layer 1 ----
    pair_kernel<<<pgrid, 256>>>(a, e, x, c1_sw, c1_sb,
                                c1_aiw, c1_aib, c1_ajw, c1_ajb, c1_ew, c1_eb,
                                pE1, 1, pAIp, pAJp);
    node_kernel<<<200, 480>>>(x, c1_nw, c1_nb, pAIp, pAJp, pX1);

    // ---- layer 2 (e_out unused downstream -> skipped) ----
    pair_kernel<<<pgrid, 256>>>(a, pE1, pX1, c2_sw, c2_sb,
                                c2_aiw, c2_aib, c2_ajw, c2_ajb, c2_ew, c2_eb,
                                nullptr, 0, pAIp, pAJp);
    node_kernel<<<200, 480>>>(pX1, c2_nw, c2_nb, pAIp, pAJp, pX2);

    // ---- dense head ----
    dim3 dgrid(50, 3);
    dense_kernel<<<dgrid, 480>>>(pX2, dw, db, out);
}